// round 14
// baseline (speedup 1.0000x reference)
#include <cuda_runtime.h>
#include <cuda.h>
#include <cuda_fp16.h>
#include <cuda_bf16.h>
#include <cstdint>

#define MDIM 8192
#define KDIM 4096
#define NDIM 4096

#define TM 128
#define TN 128
#define TK 64            /* bf16 per stage row = 128B SW128 atom */
#define STAGES 3
#define NKIT (KDIM / TK) /* 64 */

#if defined(__CUDA_ARCH__) && defined(__CUDA_ARCH_FEAT_SM103_ALL)
#define TCG 1
#else
#define TCG 0
#endif

// Scratch (__device__ globals: allocation-free rule)
__device__ __align__(1024) __nv_bfloat16 g_xbf[(size_t)MDIM * KDIM]; // 64 MB
__device__ __align__(1024) __nv_bfloat16 g_wbf[(size_t)NDIM * KDIM]; // 32 MB
__device__ float g_xscale[MDIM];
__device__ int g_ws_first;

__device__ __forceinline__ uint32_t smem_u32(const void* p) {
    uint32_t r;
    asm("{ .reg .u64 t; cvta.to.shared.u64 t, %1; cvt.u32.u64 %0, t; }" : "=r"(r) : "l"(p));
    return r;
}

// ---------------------------------------------------------------------------
// Probe: which 4096-elem fp32 input is w_scale (all in (0,0.2)) vs bias
// ---------------------------------------------------------------------------
__global__ void probe_kernel(const float* __restrict__ c0,
                             const float* __restrict__ c1) {
    __shared__ int bad0, bad1;
    if (threadIdx.x == 0) { bad0 = 0; bad1 = 0; }
    __syncthreads();
    for (int i = threadIdx.x; i < 4096; i += 256) {
        float v0 = c0[i], v1 = c1[i];
        if (!(v0 > 0.0f && v0 < 0.2f)) atomicOr(&bad0, 1);
        if (!(v1 > 0.0f && v1 < 0.2f)) atomicOr(&bad1, 1);
    }
    __syncthreads();
    if (threadIdx.x == 0) g_ws_first = (!bad0) ? 1 : ((!bad1) ? 0 : 1);
}

// ---------------------------------------------------------------------------
// Kernel 0: weights arrive as INT32 (harness materializes int8 as int32).
// Convert directly to bf16 (exact for [-128,127]).
// ---------------------------------------------------------------------------
__global__ void __launch_bounds__(256) wconv_kernel(const int* __restrict__ w32) {
    const size_t gid = (size_t)blockIdx.x * 256 + threadIdx.x;   // one per 4 values
    const int4 v = reinterpret_cast<const int4*>(w32)[gid];
    __nv_bfloat162 p0 = __floats2bfloat162_rn((float)v.x, (float)v.y);
    __nv_bfloat162 p1 = __floats2bfloat162_rn((float)v.z, (float)v.w);
    uint2 o;
    o.x = *reinterpret_cast<uint32_t*>(&p0);
    o.y = *reinterpret_cast<uint32_t*>(&p1);
    reinterpret_cast<uint2*>(g_wbf)[gid] = o;
}

// ---------------------------------------------------------------------------
// Kernel 1: per-token quantization -> bf16 quantized values + fp32 scale
// ---------------------------------------------------------------------------
__global__ void __launch_bounds__(256) quant_kernel(const float* __restrict__ x) {
    const int row = blockIdx.x;
    const int t = threadIdx.x;
    const float4* xr = reinterpret_cast<const float4*>(x + (size_t)row * KDIM);

    float4 v[4];
    float amax = 0.0f;
#pragma unroll
    for (int i = 0; i < 4; i++) {
        v[i] = xr[t + i * 256];
        amax = fmaxf(amax, fmaxf(fmaxf(fabsf(v[i].x), fabsf(v[i].y)),
                                 fmaxf(fabsf(v[i].z), fabsf(v[i].w))));
    }
#pragma unroll
    for (int o = 16; o > 0; o >>= 1) amax = fmaxf(amax, __shfl_xor_sync(0xFFFFFFFFu, amax, o));

    __shared__ float red[8];
    if ((t & 31) == 0) red[t >> 5] = amax;
    __syncthreads();
    float a = fmaxf(fmaxf(fmaxf(red[0], red[1]), fmaxf(red[2], red[3])),
                    fmaxf(fmaxf(red[4], red[5]), fmaxf(red[6], red[7])));
    a = fmaxf(a, 1e-7f);
    const float s = __fdiv_rn(a, 127.0f);
    if (t == 0) g_xscale[row] = s;

    uint2* qout = reinterpret_cast<uint2*>(g_xbf + (size_t)row * KDIM);
#pragma unroll
    for (int i = 0; i < 4; i++) {
        float q0 = (float)max(-128, min(127, __float2int_rn(__fdiv_rn(v[i].x, s))));
        float q1 = (float)max(-128, min(127, __float2int_rn(__fdiv_rn(v[i].y, s))));
        float q2 = (float)max(-128, min(127, __float2int_rn(__fdiv_rn(v[i].z, s))));
        float q3 = (float)max(-128, min(127, __float2int_rn(__fdiv_rn(v[i].w, s))));
        __nv_bfloat162 p0 = __floats2bfloat162_rn(q0, q1);
        __nv_bfloat162 p1 = __floats2bfloat162_rn(q2, q3);
        uint2 o;
        o.x = *reinterpret_cast<uint32_t*>(&p0);
        o.y = *reinterpret_cast<uint32_t*>(&p1);
        qout[t + i * 256] = o;
    }
}

// ---------------------------------------------------------------------------
// Epilogue math: ((acc_f32 * xs) * ws + bias) -> fp16 round -> fp32 store
// ---------------------------------------------------------------------------
__device__ __forceinline__ float dequant1(float accf, float xs, float ws, float b) {
    float f = __fadd_rn(__fmul_rn(__fmul_rn(accf, xs), ws), b);
    return __half2float(__float2half_rn(f));
}

// ---------------------------------------------------------------------------
// tcgen05 helpers (guarded from the compute_103 pass)
// ---------------------------------------------------------------------------
#if TCG
__device__ __forceinline__ void mbar_init(uint32_t mbar, uint32_t cnt) {
    asm volatile("mbarrier.init.shared.b64 [%0], %1;" :: "r"(mbar), "r"(cnt) : "memory");
}
__device__ __forceinline__ void mbar_expect_tx(uint32_t mbar, uint32_t bytes) {
    asm volatile("mbarrier.arrive.expect_tx.shared.b64 _, [%0], %1;" :: "r"(mbar), "r"(bytes) : "memory");
}
__device__ __forceinline__ void mbar_wait(uint32_t mbar, uint32_t parity) {
    asm volatile(
        "{\n\t.reg .pred P;\n\t"
        "WL_%=:\n\t"
        "mbarrier.try_wait.parity.acquire.cta.shared::cta.b64 P, [%0], %1, 0x989680;\n\t"
        "@P bra WD_%=;\n\t"
        "bra WL_%=;\n\t"
        "WD_%=:\n\t}"
        :: "r"(mbar), "r"(parity) : "memory");
}
__device__ __forceinline__ void tma_load_3d(uint32_t dst, const CUtensorMap* map,
                                            int x, int y, int z, uint32_t mbar) {
    asm volatile(
        "cp.async.bulk.tensor.3d.shared::cta.global.tile.mbarrier::complete_tx::bytes "
        "[%0], [%1, {%2, %3, %4}], [%5];"
        :: "r"(dst), "l"(map), "r"(x), "r"(y), "r"(z), "r"(mbar) : "memory");
}
__device__ __forceinline__ void tcgen05_alloc(uint32_t smem_dst, uint32_t ncols) {
    asm volatile("tcgen05.alloc.cta_group::1.sync.aligned.shared::cta.b32 [%0], %1;"
                 :: "r"(smem_dst), "r"(ncols) : "memory");
}
__device__ __forceinline__ void tcgen05_dealloc(uint32_t tmem, uint32_t ncols) {
    asm volatile("tcgen05.relinquish_alloc_permit.cta_group::1.sync.aligned;");
    asm volatile("tcgen05.dealloc.cta_group::1.sync.aligned.b32 %0, %1;" :: "r"(tmem), "r"(ncols));
}
__device__ __forceinline__ void tcgen05_commit(uint32_t mbar) {
    asm volatile("tcgen05.commit.cta_group::1.mbarrier::arrive::one.shared::cluster.b64 [%0];"
                 :: "r"(mbar) : "memory");
}
__device__ __forceinline__ void mma_bf16_ss(uint32_t d, uint64_t a, uint64_t b,
                                            uint32_t idesc, uint32_t acc) {
    asm volatile(
        "{\n\t.reg .pred p;\n\t"
        "setp.ne.u32 p, %5, 0;\n\t"
        "tcgen05.mma.cta_group::1.kind::f16 [%0], %1, %2, %3, {%4, %4, %4, %4}, p;\n\t}"
        :: "r"(d), "l"(a), "l"(b), "r"(idesc), "r"(0u), "r"(acc) : "memory");
}
__device__ __forceinline__ void ldtm_x32(uint32_t* r, uint32_t tmem_addr) {
    asm volatile(
        "tcgen05.ld.sync.aligned.32x32b.x32.b32 "
        "{%0, %1, %2, %3, %4, %5, %6, %7, "
        " %8, %9, %10, %11, %12, %13, %14, %15, "
        " %16, %17, %18, %19, %20, %21, %22, %23, "
        " %24, %25, %26, %27, %28, %29, %30, %31}, [%32];"
        : "=r"(r[0]),  "=r"(r[1]),  "=r"(r[2]),  "=r"(r[3]),
          "=r"(r[4]),  "=r"(r[5]),  "=r"(r[6]),  "=r"(r[7]),
          "=r"(r[8]),  "=r"(r[9]),  "=r"(r[10]), "=r"(r[11]),
          "=r"(r[12]), "=r"(r[13]), "=r"(r[14]), "=r"(r[15]),
          "=r"(r[16]), "=r"(r[17]), "=r"(r[18]), "=r"(r[19]),
          "=r"(r[20]), "=r"(r[21]), "=r"(r[22]), "=r"(r[23]),
          "=r"(r[24]), "=r"(r[25]), "=r"(r[26]), "=r"(r[27]),
          "=r"(r[28]), "=r"(r[29]), "=r"(r[30]), "=r"(r[31])
        : "r"(tmem_addr));
}
static constexpr uint64_t SMEM_DESC_BASE_SW128 =
    (uint64_t(2) << 61) | (uint64_t(1) << 46) | (uint64_t(64) << 32) | (uint64_t(1) << 16);
__device__ __forceinline__ uint64_t make_desc(uint32_t addr) {
    return SMEM_DESC_BASE_SW128 | ((uint64_t)(addr >> 4) & 0x3FFF);
}
// idesc kind::f16: dtype=F32(1)@4, atype=BF16(1)@7, btype=BF16(1)@10, N/8@17, M/16@24
static constexpr uint32_t IDESC_BF16 =
    (1u << 4) | (1u << 7) | (1u << 10) | ((TN / 8) << 17) | ((TM / 16) << 24);
#endif // TCG

// ---------------------------------------------------------------------------
// Kernel 2: tcgen05 bf16 GEMM, 3-stage pipeline, 2 CTAs/SM co-residency
// ---------------------------------------------------------------------------
#define STAGE_BYTES (TM * TK * 2)                 /* 16384 */
#define TX_BYTES (2 * STAGE_BYTES)
#define SMEM_BYTES (2048 + 2 * STAGES * STAGE_BYTES) /* ~100 KB -> 2 CTAs/SM */

__global__ void __launch_bounds__(128, 2)
gemm_kernel(const __grid_constant__ CUtensorMap tma_a,
            const __grid_constant__ CUtensorMap tma_b,
            const void* __restrict__ sc0,
            const void* __restrict__ sc1,
            float* __restrict__ out) {
    const int tid = threadIdx.x;
    const int wid = tid >> 5;
    const int lane = tid & 31;
    const int ntile = blockIdx.x;
    const int mtile = blockIdx.y;

    const int f = g_ws_first;
    const float* wscale = f ? (const float*)sc0 : (const float*)sc1;
    const float* bias   = f ? (const float*)sc1 : (const float*)sc0;  // fp32 (converted fp16)

#if TCG
    extern __shared__ char smem[];
    const uint32_t sb = smem_u32(smem);
    const uint32_t tb = (sb + 256 + 1023) & ~1023u;

    const uint32_t SM_TMEM = sb;
    auto FULL  = [&](int s) { return sb + 8 + 8u * s; };
    auto EMPTY = [&](int s) { return sb + 8 + 8u * STAGES + 8u * s; };
    const uint32_t DONE = sb + 8 + 16u * STAGES;
    auto SA    = [&](int s) { return tb + (uint32_t)s * STAGE_BYTES; };
    auto SBUF  = [&](int s) { return tb + (uint32_t)(STAGES + s) * STAGE_BYTES; };

    if (wid == 0) tcgen05_alloc(SM_TMEM, 128);
    if (tid == 0) {
        for (int s = 0; s < STAGES; s++) { mbar_init(FULL(s), 1); mbar_init(EMPTY(s), 1); }
        mbar_init(DONE, 1);
    }
    asm volatile("fence.mbarrier_init.release.cluster;" ::: "memory");
    __syncthreads();

    uint32_t tmem;
    asm volatile("ld.shared.b32 %0, [%1];" : "=r"(tmem) : "r"(SM_TMEM));

    if (tid == 0) {
        // TMA producer (explicit stage/phase cursor; STAGES not a power of 2)
        int s = 0, ph = 0;
        for (int k = 0; k < NKIT; k++) {
            if (k >= STAGES) mbar_wait(EMPTY(s), ph ^ 1);
            mbar_expect_tx(FULL(s), TX_BYTES);
            tma_load_3d(SA(s),   &tma_a, k * TK, mtile * TM, 0, FULL(s));
            tma_load_3d(SBUF(s), &tma_b, k * TK, ntile * TN, 0, FULL(s));
            if (++s == STAGES) { s = 0; ph ^= 1; }
        }
    } else if (tid == 32) {
        // MMA issuer: 4 x K16 dispatches per stage (desc step = 32B = 2 units)
        int s = 0, ph = 0;
        for (int k = 0; k < NKIT; k++) {
            mbar_wait(FULL(s), ph);
            const uint64_t ad = make_desc(SA(s));
            const uint64_t bd = make_desc(SBUF(s));
#pragma unroll
            for (int j = 0; j < 4; j++)
                mma_bf16_ss(tmem, ad + j * 2, bd + j * 2, IDESC_BF16,
                            (k > 0 || j > 0) ? 1u : 0u);
            tcgen05_commit(EMPTY(s));
            if (++s == STAGES) { s = 0; ph ^= 1; }
        }
        tcgen05_commit(DONE);   // one-shot: fires after ALL MMAs complete
    }

    mbar_wait(DONE, 0);
    asm volatile("tcgen05.fence::after_thread_sync;" ::: "memory");

    const int m = mtile * TM + wid * 32 + lane;
    const float xs = g_xscale[m];
    float* orow = out + (size_t)m * NDIM + (size_t)ntile * TN;

#pragma unroll
    for (int ch = 0; ch < 4; ch++) {
        uint32_t d[32];
        ldtm_x32(d, tmem + ch * 32);
        asm volatile("tcgen05.wait::ld.sync.aligned;" ::: "memory");
#pragma unroll
        for (int c = 0; c < 32; c += 2) {
            const int n = ntile * TN + ch * 32 + c;
            float2 p;
            p.x = dequant1(__uint_as_float(d[c]),     xs, __ldg(wscale + n),     __ldg(bias + n));
            p.y = dequant1(__uint_as_float(d[c + 1]), xs, __ldg(wscale + n + 1), __ldg(bias + n + 1));
            *reinterpret_cast<float2*>(orow + ch * 32 + c) = p;
        }
    }

    __syncthreads();
    if (wid == 0) tcgen05_dealloc(tmem, 128);
#else
    // compute_103 pass fallback (never executed on GB300). Correct naive GEMM.
    (void)tma_a; (void)tma_b;
    for (int idx = tid; idx < TM * TN; idx += 128) {
        const int r = mtile * TM + (idx >> 7);
        const int c = ntile * TN + (idx & 127);
        const __nv_bfloat16* ar = g_xbf + (size_t)r * KDIM;
        const __nv_bfloat16* br = g_wbf + (size_t)c * KDIM;
        float acc = 0.0f;
        for (int k = 0; k < KDIM; k++)
            acc += __bfloat162float(ar[k]) * __bfloat162float(br[k]);
        out[(size_t)r * NDIM + c] = dequant1(acc, g_xscale[r], wscale[c], bias[c]);
    }
#endif
}

// ---------------------------------------------------------------------------
// Host launch
// ---------------------------------------------------------------------------
typedef CUresult (CUDAAPI *PFN_tmapEnc)(
    CUtensorMap*, CUtensorMapDataType, cuuint32_t, void*,
    const cuuint64_t*, const cuuint64_t*, const cuuint32_t*, const cuuint32_t*,
    CUtensorMapInterleave, CUtensorMapSwizzle, CUtensorMapL2promotion,
    CUtensorMapFloatOOBfill);

extern "C" void kernel_launch(void* const* d_in, const int* in_sizes, int n_in,
                              void* d_out, int out_size) {
    (void)out_size;
    int xi = -1, wi = -1, si[2] = {-1, -1};
    int nsi = 0;
    for (int i = 0; i < n_in; i++) {
        if (in_sizes[i] == 33554432) xi = i;
        else if (in_sizes[i] == 16777216) wi = i;
        else if (nsi < 2) si[nsi++] = i;
    }
    if (xi < 0 || wi < 0 || nsi < 2) { xi = 0; wi = 1; si[0] = 2; si[1] = 3; }

    const float* x    = (const float*)d_in[xi];
    const int*   w32  = (const int*)d_in[wi];      // int8 materialized as int32
    const void*  sc0  = d_in[si[0]];
    const void*  sc1  = d_in[si[1]];
    float*       out  = (float*)d_out;

    probe_kernel<<<1, 256>>>((const float*)sc0, (const float*)sc1);
    wconv_kernel<<<(NDIM * (size_t)KDIM) / (256 * 4), 256>>>(w32);
    quant_kernel<<<MDIM, 256>>>(x);

    void* xbf_ptr = nullptr;
    void* wbf_ptr = nullptr;
    cudaGetSymbolAddress(&xbf_ptr, g_xbf);
    cudaGetSymbolAddress(&wbf_ptr, g_wbf);

    PFN_tmapEnc enc = nullptr;
    cudaDriverEntryPointQueryResult qr;
    cudaGetDriverEntryPointByVersion("cuTensorMapEncodeTiled", (void**)&enc, 12000,
                                     cudaEnableDefault, &qr);

    CUtensorMap ta, tbm;
    cuuint64_t dimsA[3] = {KDIM, MDIM, 1};
    cuuint64_t strA[2]  = {(cuuint64_t)KDIM * 2, (cuuint64_t)KDIM * MDIM * 2};
    cuuint64_t dimsB[3] = {KDIM, NDIM, 1};
    cuuint64_t strB[2]  = {(cuuint64_t)KDIM * 2, (cuuint64_t)KDIM * NDIM * 2};
    cuuint32_t box[3]   = {TK, TM, 1};   /* 64 bf16 = 128B = SW128 atom */
    cuuint32_t es[3]    = {1, 1, 1};
    if (enc) {
        enc(&ta, CU_TENSOR_MAP_DATA_TYPE_BFLOAT16, 3, xbf_ptr, dimsA, strA, box, es,
            CU_TENSOR_MAP_INTERLEAVE_NONE, CU_TENSOR_MAP_SWIZZLE_128B,
            CU_TENSOR_MAP_L2_PROMOTION_L2_128B, CU_TENSOR_MAP_FLOAT_OOB_FILL_NONE);
        enc(&tbm, CU_TENSOR_MAP_DATA_TYPE_BFLOAT16, 3, wbf_ptr, dimsB, strB, box, es,
            CU_TENSOR_MAP_INTERLEAVE_NONE, CU_TENSOR_MAP_SWIZZLE_128B,
            CU_TENSOR_MAP_L2_PROMOTION_L2_128B, CU_TENSOR_MAP_FLOAT_OOB_FILL_NONE);
    }

    cudaFuncSetAttribute(gemm_kernel, cudaFuncAttributeMaxDynamicSharedMemorySize, SMEM_BYTES);
    dim3 grid(NDIM / TN, MDIM / TM);
    gemm_kernel<<<grid, 128, SMEM_BYTES>>>(ta, tbm, sc0, sc1, out);
}

// round 15
// speedup vs baseline: 1.9584x; 1.9584x over previous
#include <cuda_runtime.h>
#include <cuda.h>
#include <cuda_fp16.h>
#include <cuda_bf16.h>
#include <cstdint>

#define MDIM 8192
#define KDIM 4096
#define NDIM 4096

#define TM 128
#define TN 256
#define TK 64            /* bf16 per stage row = 128B SW128 atom */
#define STAGES 4
#define NKIT (KDIM / TK) /* 64 */

#if defined(__CUDA_ARCH__) && defined(__CUDA_ARCH_FEAT_SM103_ALL)
#define TCG 1
#else
#define TCG 0
#endif

// Scratch (__device__ globals: allocation-free rule)
__device__ __align__(1024) __nv_bfloat16 g_xbf[(size_t)MDIM * KDIM]; // 64 MB
__device__ __align__(1024) __nv_bfloat16 g_wbf[(size_t)NDIM * KDIM]; // 32 MB
__device__ float g_xscale[MDIM];
__device__ int g_ws_first;

__device__ __forceinline__ uint32_t smem_u32(const void* p) {
    uint32_t r;
    asm("{ .reg .u64 t; cvta.to.shared.u64 t, %1; cvt.u32.u64 %0, t; }" : "=r"(r) : "l"(p));
    return r;
}

// ---------------------------------------------------------------------------
// Probe: which 4096-elem fp32 input is w_scale (all in (0,0.2)) vs bias
// ---------------------------------------------------------------------------
__global__ void probe_kernel(const float* __restrict__ c0,
                             const float* __restrict__ c1) {
    __shared__ int bad0, bad1;
    if (threadIdx.x == 0) { bad0 = 0; bad1 = 0; }
    __syncthreads();
    for (int i = threadIdx.x; i < 4096; i += 256) {
        float v0 = c0[i], v1 = c1[i];
        if (!(v0 > 0.0f && v0 < 0.2f)) atomicOr(&bad0, 1);
        if (!(v1 > 0.0f && v1 < 0.2f)) atomicOr(&bad1, 1);
    }
    __syncthreads();
    if (threadIdx.x == 0) g_ws_first = (!bad0) ? 1 : ((!bad1) ? 0 : 1);
}

// ---------------------------------------------------------------------------
// Kernel 0: weights arrive as INT32 (harness materializes int8 as int32).
// Convert directly to bf16 (exact for [-128,127]).
// ---------------------------------------------------------------------------
__global__ void __launch_bounds__(256) wconv_kernel(const int* __restrict__ w32) {
    const size_t gid = (size_t)blockIdx.x * 256 + threadIdx.x;   // one per 4 values
    const int4 v = reinterpret_cast<const int4*>(w32)[gid];
    __nv_bfloat162 p0 = __floats2bfloat162_rn((float)v.x, (float)v.y);
    __nv_bfloat162 p1 = __floats2bfloat162_rn((float)v.z, (float)v.w);
    uint2 o;
    o.x = *reinterpret_cast<uint32_t*>(&p0);
    o.y = *reinterpret_cast<uint32_t*>(&p1);
    reinterpret_cast<uint2*>(g_wbf)[gid] = o;
}

// ---------------------------------------------------------------------------
// Kernel 1: per-token quantization -> bf16 quantized values + fp32 scale
// ---------------------------------------------------------------------------
__global__ void __launch_bounds__(256) quant_kernel(const float* __restrict__ x) {
    const int row = blockIdx.x;
    const int t = threadIdx.x;
    const float4* xr = reinterpret_cast<const float4*>(x + (size_t)row * KDIM);

    float4 v[4];
    float amax = 0.0f;
#pragma unroll
    for (int i = 0; i < 4; i++) {
        v[i] = xr[t + i * 256];
        amax = fmaxf(amax, fmaxf(fmaxf(fabsf(v[i].x), fabsf(v[i].y)),
                                 fmaxf(fabsf(v[i].z), fabsf(v[i].w))));
    }
#pragma unroll
    for (int o = 16; o > 0; o >>= 1) amax = fmaxf(amax, __shfl_xor_sync(0xFFFFFFFFu, amax, o));

    __shared__ float red[8];
    if ((t & 31) == 0) red[t >> 5] = amax;
    __syncthreads();
    float a = fmaxf(fmaxf(fmaxf(red[0], red[1]), fmaxf(red[2], red[3])),
                    fmaxf(fmaxf(red[4], red[5]), fmaxf(red[6], red[7])));
    a = fmaxf(a, 1e-7f);
    const float s = __fdiv_rn(a, 127.0f);
    if (t == 0) g_xscale[row] = s;

    uint2* qout = reinterpret_cast<uint2*>(g_xbf + (size_t)row * KDIM);
#pragma unroll
    for (int i = 0; i < 4; i++) {
        float q0 = (float)max(-128, min(127, __float2int_rn(__fdiv_rn(v[i].x, s))));
        float q1 = (float)max(-128, min(127, __float2int_rn(__fdiv_rn(v[i].y, s))));
        float q2 = (float)max(-128, min(127, __float2int_rn(__fdiv_rn(v[i].z, s))));
        float q3 = (float)max(-128, min(127, __float2int_rn(__fdiv_rn(v[i].w, s))));
        __nv_bfloat162 p0 = __floats2bfloat162_rn(q0, q1);
        __nv_bfloat162 p1 = __floats2bfloat162_rn(q2, q3);
        uint2 o;
        o.x = *reinterpret_cast<uint32_t*>(&p0);
        o.y = *reinterpret_cast<uint32_t*>(&p1);
        qout[t + i * 256] = o;
    }
}

// ---------------------------------------------------------------------------
// Epilogue math: ((acc_f32 * xs) * ws + bias) -> fp16 round -> fp32 store
// ---------------------------------------------------------------------------
__device__ __forceinline__ float dequant1(float accf, float xs, float ws, float b) {
    float f = __fadd_rn(__fmul_rn(__fmul_rn(accf, xs), ws), b);
    return __half2float(__float2half_rn(f));
}

// ---------------------------------------------------------------------------
// tcgen05 helpers (guarded from the compute_103 pass)
// ---------------------------------------------------------------------------
#if TCG
__device__ __forceinline__ void mbar_init(uint32_t mbar, uint32_t cnt) {
    asm volatile("mbarrier.init.shared.b64 [%0], %1;" :: "r"(mbar), "r"(cnt) : "memory");
}
__device__ __forceinline__ void mbar_expect_tx(uint32_t mbar, uint32_t bytes) {
    asm volatile("mbarrier.arrive.expect_tx.shared.b64 _, [%0], %1;" :: "r"(mbar), "r"(bytes) : "memory");
}
__device__ __forceinline__ void mbar_wait(uint32_t mbar, uint32_t parity) {
    asm volatile(
        "{\n\t.reg .pred P;\n\t"
        "WL_%=:\n\t"
        "mbarrier.try_wait.parity.acquire.cta.shared::cta.b64 P, [%0], %1, 0x989680;\n\t"
        "@P bra WD_%=;\n\t"
        "bra WL_%=;\n\t"
        "WD_%=:\n\t}"
        :: "r"(mbar), "r"(parity) : "memory");
}
__device__ __forceinline__ void tma_load_3d(uint32_t dst, const CUtensorMap* map,
                                            int x, int y, int z, uint32_t mbar) {
    asm volatile(
        "cp.async.bulk.tensor.3d.shared::cta.global.tile.mbarrier::complete_tx::bytes "
        "[%0], [%1, {%2, %3, %4}], [%5];"
        :: "r"(dst), "l"(map), "r"(x), "r"(y), "r"(z), "r"(mbar) : "memory");
}
__device__ __forceinline__ void tcgen05_alloc(uint32_t smem_dst, uint32_t ncols) {
    asm volatile("tcgen05.alloc.cta_group::1.sync.aligned.shared::cta.b32 [%0], %1;"
                 :: "r"(smem_dst), "r"(ncols) : "memory");
}
__device__ __forceinline__ void tcgen05_dealloc(uint32_t tmem, uint32_t ncols) {
    asm volatile("tcgen05.relinquish_alloc_permit.cta_group::1.sync.aligned;");
    asm volatile("tcgen05.dealloc.cta_group::1.sync.aligned.b32 %0, %1;" :: "r"(tmem), "r"(ncols));
}
__device__ __forceinline__ void tcgen05_commit(uint32_t mbar) {
    asm volatile("tcgen05.commit.cta_group::1.mbarrier::arrive::one.shared::cluster.b64 [%0];"
                 :: "r"(mbar) : "memory");
}
__device__ __forceinline__ void mma_bf16_ss(uint32_t d, uint64_t a, uint64_t b,
                                            uint32_t idesc, uint32_t acc) {
    asm volatile(
        "{\n\t.reg .pred p;\n\t"
        "setp.ne.u32 p, %5, 0;\n\t"
        "tcgen05.mma.cta_group::1.kind::f16 [%0], %1, %2, %3, {%4, %4, %4, %4}, p;\n\t}"
        :: "r"(d), "l"(a), "l"(b), "r"(idesc), "r"(0u), "r"(acc) : "memory");
}
__device__ __forceinline__ void ldtm_x32(uint32_t* r, uint32_t tmem_addr) {
    asm volatile(
        "tcgen05.ld.sync.aligned.32x32b.x32.b32 "
        "{%0, %1, %2, %3, %4, %5, %6, %7, "
        " %8, %9, %10, %11, %12, %13, %14, %15, "
        " %16, %17, %18, %19, %20, %21, %22, %23, "
        " %24, %25, %26, %27, %28, %29, %30, %31}, [%32];"
        : "=r"(r[0]),  "=r"(r[1]),  "=r"(r[2]),  "=r"(r[3]),
          "=r"(r[4]),  "=r"(r[5]),  "=r"(r[6]),  "=r"(r[7]),
          "=r"(r[8]),  "=r"(r[9]),  "=r"(r[10]), "=r"(r[11]),
          "=r"(r[12]), "=r"(r[13]), "=r"(r[14]), "=r"(r[15]),
          "=r"(r[16]), "=r"(r[17]), "=r"(r[18]), "=r"(r[19]),
          "=r"(r[20]), "=r"(r[21]), "=r"(r[22]), "=r"(r[23]),
          "=r"(r[24]), "=r"(r[25]), "=r"(r[26]), "=r"(r[27]),
          "=r"(r[28]), "=r"(r[29]), "=r"(r[30]), "=r"(r[31])
        : "r"(tmem_addr));
}
static constexpr uint64_t SMEM_DESC_BASE_SW128 =
    (uint64_t(2) << 61) | (uint64_t(1) << 46) | (uint64_t(64) << 32) | (uint64_t(1) << 16);
__device__ __forceinline__ uint64_t make_desc(uint32_t addr) {
    return SMEM_DESC_BASE_SW128 | ((uint64_t)(addr >> 4) & 0x3FFF);
}
// idesc kind::f16: dtype=F32(1)@4, atype=BF16(1)@7, btype=BF16(1)@10, N/8@17, M/16@24
static constexpr uint32_t IDESC_BF16 =
    (1u << 4) | (1u << 7) | (1u << 10) | ((TN / 8) << 17) | ((TM / 16) << 24);
#endif // TCG

// ---------------------------------------------------------------------------
// Kernel 2: tcgen05 bf16 GEMM, 128x256 tile, 4-stage TMA pipeline
// ---------------------------------------------------------------------------
#define A_STAGE_BYTES (TM * TK * 2)               /* 16384 */
#define B_STAGE_BYTES (TN * TK * 2)               /* 32768 */
#define TX_BYTES (A_STAGE_BYTES + B_STAGE_BYTES)
#define SMEM_BYTES (2048 + STAGES * (A_STAGE_BYTES + B_STAGE_BYTES)) /* ~198 KB */

__global__ void __launch_bounds__(128, 1)
gemm_kernel(const __grid_constant__ CUtensorMap tma_a,
            const __grid_constant__ CUtensorMap tma_b,
            const void* __restrict__ sc0,
            const void* __restrict__ sc1,
            float* __restrict__ out) {
    const int tid = threadIdx.x;
    const int wid = tid >> 5;
    const int lane = tid & 31;
    const int ntile = blockIdx.x;
    const int mtile = blockIdx.y;

    const int f = g_ws_first;
    const float* wscale = f ? (const float*)sc0 : (const float*)sc1;
    const float* bias   = f ? (const float*)sc1 : (const float*)sc0;  // fp32 (converted fp16)

#if TCG
    extern __shared__ char smem[];
    const uint32_t sb = smem_u32(smem);
    const uint32_t tb = (sb + 256 + 1023) & ~1023u;

    const uint32_t SM_TMEM = sb;
    auto FULL  = [&](int s) { return sb + 8 + 8u * s; };
    auto EMPTY = [&](int s) { return sb + 8 + 8u * STAGES + 8u * s; };
    const uint32_t DONE = sb + 8 + 16u * STAGES;
    auto SA    = [&](int s) { return tb + (uint32_t)s * A_STAGE_BYTES; };
    auto SBUF  = [&](int s) { return tb + (uint32_t)STAGES * A_STAGE_BYTES
                                        + (uint32_t)s * B_STAGE_BYTES; };

    if (wid == 0) tcgen05_alloc(SM_TMEM, 256);
    if (tid == 0) {
        for (int s = 0; s < STAGES; s++) { mbar_init(FULL(s), 1); mbar_init(EMPTY(s), 1); }
        mbar_init(DONE, 1);
    }
    asm volatile("fence.mbarrier_init.release.cluster;" ::: "memory");
    __syncthreads();

    uint32_t tmem;
    asm volatile("ld.shared.b32 %0, [%1];" : "=r"(tmem) : "r"(SM_TMEM));

    if (tid == 0) {
        // TMA producer (STAGES=4 power-of-2 cursors)
        for (int k = 0; k < NKIT; k++) {
            const int s = k & (STAGES - 1);
            if (k >= STAGES) mbar_wait(EMPTY(s), ((k >> 2) - 1) & 1);
            mbar_expect_tx(FULL(s), TX_BYTES);
            tma_load_3d(SA(s),   &tma_a, k * TK, mtile * TM, 0, FULL(s));
            tma_load_3d(SBUF(s), &tma_b, k * TK, ntile * TN, 0, FULL(s));
        }
    } else if (tid == 32) {
        // MMA issuer: 4 x K16 dispatches per stage (desc step = 32B = 2 units)
        for (int k = 0; k < NKIT; k++) {
            const int s = k & (STAGES - 1);
            mbar_wait(FULL(s), (k >> 2) & 1);
            const uint64_t ad = make_desc(SA(s));
            const uint64_t bd = make_desc(SBUF(s));
#pragma unroll
            for (int j = 0; j < 4; j++)
                mma_bf16_ss(tmem, ad + j * 2, bd + j * 2, IDESC_BF16,
                            (k > 0 || j > 0) ? 1u : 0u);
            tcgen05_commit(EMPTY(s));
        }
        tcgen05_commit(DONE);   // one-shot: fires after ALL MMAs complete
    }

    mbar_wait(DONE, 0);
    asm volatile("tcgen05.fence::after_thread_sync;" ::: "memory");

    const int m = mtile * TM + wid * 32 + lane;
    const float xs = g_xscale[m];
    float* orow = out + (size_t)m * NDIM + (size_t)ntile * TN;

#pragma unroll
    for (int ch = 0; ch < TN / 32; ch++) {
        uint32_t d[32];
        ldtm_x32(d, tmem + ch * 32);
        asm volatile("tcgen05.wait::ld.sync.aligned;" ::: "memory");
#pragma unroll
        for (int c = 0; c < 32; c += 2) {
            const int n = ntile * TN + ch * 32 + c;
            float2 p;
            p.x = dequant1(__uint_as_float(d[c]),     xs, __ldg(wscale + n),     __ldg(bias + n));
            p.y = dequant1(__uint_as_float(d[c + 1]), xs, __ldg(wscale + n + 1), __ldg(bias + n + 1));
            *reinterpret_cast<float2*>(orow + ch * 32 + c) = p;
        }
    }

    __syncthreads();
    if (wid == 0) tcgen05_dealloc(tmem, 256);
#else
    // compute_103 pass fallback (never executed on GB300). Correct naive GEMM.
    (void)tma_a; (void)tma_b;
    for (int idx = tid; idx < TM * TN; idx += 128) {
        const int r = mtile * TM + (idx / TN);
        const int c = ntile * TN + (idx % TN);
        const __nv_bfloat16* ar = g_xbf + (size_t)r * KDIM;
        const __nv_bfloat16* br = g_wbf + (size_t)c * KDIM;
        float acc = 0.0f;
        for (int k = 0; k < KDIM; k++)
            acc += __bfloat162float(ar[k]) * __bfloat162float(br[k]);
        out[(size_t)r * NDIM + c] = dequant1(acc, g_xscale[r], wscale[c], bias[c]);
    }
#endif
}

// ---------------------------------------------------------------------------
// Host launch
// ---------------------------------------------------------------------------
typedef CUresult (CUDAAPI *PFN_tmapEnc)(
    CUtensorMap*, CUtensorMapDataType, cuuint32_t, void*,
    const cuuint64_t*, const cuuint64_t*, const cuuint32_t*, const cuuint32_t*,
    CUtensorMapInterleave, CUtensorMapSwizzle, CUtensorMapL2promotion,
    CUtensorMapFloatOOBfill);

extern "C" void kernel_launch(void* const* d_in, const int* in_sizes, int n_in,
                              void* d_out, int out_size) {
    (void)out_size;
    int xi = -1, wi = -1, si[2] = {-1, -1};
    int nsi = 0;
    for (int i = 0; i < n_in; i++) {
        if (in_sizes[i] == 33554432) xi = i;
        else if (in_sizes[i] == 16777216) wi = i;
        else if (nsi < 2) si[nsi++] = i;
    }
    if (xi < 0 || wi < 0 || nsi < 2) { xi = 0; wi = 1; si[0] = 2; si[1] = 3; }

    const float* x    = (const float*)d_in[xi];
    const int*   w32  = (const int*)d_in[wi];      // int8 materialized as int32
    const void*  sc0  = d_in[si[0]];
    const void*  sc1  = d_in[si[1]];
    float*       out  = (float*)d_out;

    probe_kernel<<<1, 256>>>((const float*)sc0, (const float*)sc1);
    wconv_kernel<<<(NDIM * (size_t)KDIM) / (256 * 4), 256>>>(w32);
    quant_kernel<<<MDIM, 256>>>(x);

    void* xbf_ptr = nullptr;
    void* wbf_ptr = nullptr;
    cudaGetSymbolAddress(&xbf_ptr, g_xbf);
    cudaGetSymbolAddress(&wbf_ptr, g_wbf);

    PFN_tmapEnc enc = nullptr;
    cudaDriverEntryPointQueryResult qr;
    cudaGetDriverEntryPointByVersion("cuTensorMapEncodeTiled", (void**)&enc, 12000,
                                     cudaEnableDefault, &qr);

    CUtensorMap ta, tbm;
    cuuint64_t dimsA[3] = {KDIM, MDIM, 1};
    cuuint64_t strA[2]  = {(cuuint64_t)KDIM * 2, (cuuint64_t)KDIM * MDIM * 2};
    cuuint64_t dimsB[3] = {KDIM, NDIM, 1};
    cuuint64_t strB[2]  = {(cuuint64_t)KDIM * 2, (cuuint64_t)KDIM * NDIM * 2};
    cuuint32_t boxA[3]  = {TK, TM, 1};   /* 64 bf16 = 128B = SW128 atom */
    cuuint32_t boxB[3]  = {TK, TN, 1};   /* 256-row box (TMA max) */
    cuuint32_t es[3]    = {1, 1, 1};
    if (enc) {
        enc(&ta, CU_TENSOR_MAP_DATA_TYPE_BFLOAT16, 3, xbf_ptr, dimsA, strA, boxA, es,
            CU_TENSOR_MAP_INTERLEAVE_NONE, CU_TENSOR_MAP_SWIZZLE_128B,
            CU_TENSOR_MAP_L2_PROMOTION_L2_128B, CU_TENSOR_MAP_FLOAT_OOB_FILL_NONE);
        enc(&tbm, CU_TENSOR_MAP_DATA_TYPE_BFLOAT16, 3, wbf_ptr, dimsB, strB, boxB, es,
            CU_TENSOR_MAP_INTERLEAVE_NONE, CU_TENSOR_MAP_SWIZZLE_128B,
            CU_TENSOR_MAP_L2_PROMOTION_L2_128B, CU_TENSOR_MAP_FLOAT_OOB_FILL_NONE);
    }

    cudaFuncSetAttribute(gemm_kernel, cudaFuncAttributeMaxDynamicSharedMemorySize, SMEM_BYTES);
    dim3 grid(NDIM / TN, MDIM / TM);
    gemm_kernel<<<grid, 128, SMEM_BYTES>>>(ta, tbm, sc0, sc1, out);
}